// round 6
// baseline (speedup 1.0000x reference)
#include <cuda_runtime.h>
#include <cuda_bf16.h>
#include <cstdint>

// Shapes (fixed by the problem)
#define L_DIM 4
#define B_DIM 8
#define C_DIM 256
#define HW    4096           // 64*64
#define LBC   (L_DIM * B_DIM * C_DIM)   // 8192

// Scratch in device globals (no allocations allowed)
__device__ float g_gap[LBC];
__device__ float g_attn[LBC];

// ---------------------------------------------------------------------------
// Kernel 1: GAP over H,W. One block per (l,b,c) plane (4096 contiguous f32).
// 128 threads, each loads 8 float4 (32 floats), warp-shuffle reduce.
// (Unchanged — ~6 TB/s.)
// ---------------------------------------------------------------------------
__global__ __launch_bounds__(128) void gap_kernel(const float* __restrict__ in) {
    const int bc = blockIdx.x;
    const float4* p = reinterpret_cast<const float4*>(in) + (size_t)bc * (HW / 4);
    const int t = threadIdx.x;

    float s = 0.0f;
#pragma unroll
    for (int k = 0; k < 8; ++k) {
        float4 v = p[t + k * 128];
        s += (v.x + v.y) + (v.z + v.w);
    }
#pragma unroll
    for (int o = 16; o > 0; o >>= 1)
        s += __shfl_xor_sync(0xffffffffu, s, o);

    __shared__ float sh[4];
    if ((t & 31) == 0) sh[t >> 5] = s;
    __syncthreads();
    if (t == 0)
        g_gap[bc] = (sh[0] + sh[1] + sh[2] + sh[3]) * (1.0f / (float)HW);
}

// ---------------------------------------------------------------------------
// Kernel 2: scores = gap @ W^T, softmax over L per (b, d). (Unchanged.)
// ---------------------------------------------------------------------------
__global__ __launch_bounds__(C_DIM) void attn_kernel(const float* __restrict__ Wlin) {
    const int b = blockIdx.x;
    const int t = threadIdx.x;
    const int warp = t >> 5;
    const int lane = t & 31;

    __shared__ float gs[L_DIM][C_DIM];
    for (int i = t; i < L_DIM * C_DIM; i += blockDim.x) {
        int l = i >> 8;
        int c = i & 255;
        gs[l][c] = g_gap[(l * B_DIM + b) * C_DIM + c];
    }
    __shared__ float s_scores[L_DIM][C_DIM];
    __syncthreads();

#pragma unroll 1
    for (int dd = 0; dd < 32; ++dd) {
        const int d = warp * 32 + dd;
        const float* wr = Wlin + (size_t)d * C_DIM;
        float acc0 = 0.f, acc1 = 0.f, acc2 = 0.f, acc3 = 0.f;
#pragma unroll
        for (int j = 0; j < C_DIM / 32; ++j) {
            const int c = lane + 32 * j;
            float w = wr[c];
            acc0 = fmaf(w, gs[0][c], acc0);
            acc1 = fmaf(w, gs[1][c], acc1);
            acc2 = fmaf(w, gs[2][c], acc2);
            acc3 = fmaf(w, gs[3][c], acc3);
        }
#pragma unroll
        for (int o = 16; o > 0; o >>= 1) {
            acc0 += __shfl_xor_sync(0xffffffffu, acc0, o);
            acc1 += __shfl_xor_sync(0xffffffffu, acc1, o);
            acc2 += __shfl_xor_sync(0xffffffffu, acc2, o);
            acc3 += __shfl_xor_sync(0xffffffffu, acc3, o);
        }
        if (lane == 0) {
            s_scores[0][d] = acc0;
            s_scores[1][d] = acc1;
            s_scores[2][d] = acc2;
            s_scores[3][d] = acc3;
        }
    }
    __syncthreads();

    const int d = t;
    float a0 = s_scores[0][d], a1 = s_scores[1][d];
    float a2 = s_scores[2][d], a3 = s_scores[3][d];
    float m = fmaxf(fmaxf(a0, a1), fmaxf(a2, a3));
    float e0 = __expf(a0 - m), e1 = __expf(a1 - m);
    float e2 = __expf(a2 - m), e3 = __expf(a3 - m);
    float inv = 1.0f / (e0 + e1 + e2 + e3);
    g_attn[(0 * B_DIM + b) * C_DIM + d] = e0 * inv;
    g_attn[(1 * B_DIM + b) * C_DIM + d] = e1 * inv;
    g_attn[(2 * B_DIM + b) * C_DIM + d] = e2 * inv;
    g_attn[(3 * B_DIM + b) * C_DIM + d] = e3 * inv;
}

// ---------------------------------------------------------------------------
// Kernel 3 (TMA STORE): out = in * attn. Reads stay on the proven LDG.128
// path (front-batched, MLP=8). Results go to a 16 KB SMEM tile via STS.128
// (issue-only, no L1tex/LTS queue), then ONE cp.async.bulk store ships the
// whole plane SMEM->GMEM, replacing 1024 expensive STG.128 per block with a
// single bulk-TMA op. 8192 concurrent blocks supply the TMA MLP.
// ---------------------------------------------------------------------------
__global__ __launch_bounds__(128) void scale_kernel(const float* __restrict__ in,
                                                    float* __restrict__ out) {
    __shared__ alignas(128) float4 tile[HW / 4];   // 16 KB
    const int bc = blockIdx.x;
    const float4* p = reinterpret_cast<const float4*>(in) + (size_t)bc * (HW / 4);
    float4* o = reinterpret_cast<float4*>(out) + (size_t)bc * (HW / 4);
    const int t = threadIdx.x;

    // Front-batch all 8 loads (independent LDG.128s in flight).
    float4 v0 = p[t + 0 * 128];
    float4 v1 = p[t + 1 * 128];
    float4 v2 = p[t + 2 * 128];
    float4 v3 = p[t + 3 * 128];
    float4 v4 = p[t + 4 * 128];
    float4 v5 = p[t + 5 * 128];
    float4 v6 = p[t + 6 * 128];
    float4 v7 = p[t + 7 * 128];

    const float a = __ldg(&g_attn[bc]);

    v0.x *= a; v0.y *= a; v0.z *= a; v0.w *= a;
    v1.x *= a; v1.y *= a; v1.z *= a; v1.w *= a;
    v2.x *= a; v2.y *= a; v2.z *= a; v2.w *= a;
    v3.x *= a; v3.y *= a; v3.z *= a; v3.w *= a;
    v4.x *= a; v4.y *= a; v4.z *= a; v4.w *= a;
    v5.x *= a; v5.y *= a; v5.z *= a; v5.w *= a;
    v6.x *= a; v6.y *= a; v6.z *= a; v6.w *= a;
    v7.x *= a; v7.y *= a; v7.z *= a; v7.w *= a;

    tile[t + 0 * 128] = v0;
    tile[t + 1 * 128] = v1;
    tile[t + 2 * 128] = v2;
    tile[t + 3 * 128] = v3;
    tile[t + 4 * 128] = v4;
    tile[t + 5 * 128] = v5;
    tile[t + 6 * 128] = v6;
    tile[t + 7 * 128] = v7;

    // Make generic-proxy smem writes visible to the async (TMA) proxy.
    asm volatile("fence.proxy.async.shared::cta;" ::: "memory");
    __syncthreads();

    if (t == 0) {
        uint32_t saddr = (uint32_t)__cvta_generic_to_shared(tile);
        asm volatile(
            "cp.async.bulk.global.shared::cta.bulk_group [%0], [%1], %2;"
            :: "l"(o), "r"(saddr), "r"((int)(HW * 4)) : "memory");
        asm volatile("cp.async.bulk.commit_group;" ::: "memory");
        // Block must not retire while the bulk store still reads its SMEM.
        asm volatile("cp.async.bulk.wait_group 0;" ::: "memory");
    }
}

extern "C" void kernel_launch(void* const* d_in, const int* in_sizes, int n_in,
                              void* d_out, int out_size) {
    const float* inputs = (const float*)d_in[0];   // [L,B,C,H,W] f32
    const float* Wlin   = (const float*)d_in[1];   // [C,C] f32
    float* out = (float*)d_out;

    gap_kernel<<<LBC, 128>>>(inputs);
    attn_kernel<<<B_DIM, C_DIM>>>(Wlin);
    scale_kernel<<<LBC, 128>>>(inputs, out);
}

// round 7
// speedup vs baseline: 1.4527x; 1.4527x over previous
#include <cuda_runtime.h>
#include <cuda_bf16.h>
#include <cstdint>

// Shapes (fixed by the problem)
#define L_DIM 4
#define B_DIM 8
#define C_DIM 256
#define HW    4096           // 64*64
#define LBC   (L_DIM * B_DIM * C_DIM)   // 8192

// Scratch in device globals (no allocations allowed)
__device__ float g_gap[LBC];

// ---------------------------------------------------------------------------
// Kernel 1: GAP over H,W. One block per (l,b,c) plane (4096 contiguous f32).
// 128 threads, each loads 8 float4 (32 floats), warp-shuffle reduce.
// (Unchanged — ~6 TB/s.)
// ---------------------------------------------------------------------------
__global__ __launch_bounds__(128) void gap_kernel(const float* __restrict__ in) {
    const int bc = blockIdx.x;
    const float4* p = reinterpret_cast<const float4*>(in) + (size_t)bc * (HW / 4);
    const int t = threadIdx.x;

    float s = 0.0f;
#pragma unroll
    for (int k = 0; k < 8; ++k) {
        float4 v = p[t + k * 128];
        s += (v.x + v.y) + (v.z + v.w);
    }
#pragma unroll
    for (int o = 16; o > 0; o >>= 1)
        s += __shfl_xor_sync(0xffffffffu, s, o);

    __shared__ float sh[4];
    if ((t & 31) == 0) sh[t >> 5] = s;
    __syncthreads();
    if (t == 0)
        g_gap[bc] = (sh[0] + sh[1] + sh[2] + sh[3]) * (1.0f / (float)HW);
}

// ---------------------------------------------------------------------------
// Kernel 2 (FUSED attn+scale): each block handles one (l,b,c) plane.
// Prologue: front-batch the 8 plane LDG.128s. While they're in flight,
// redundantly compute the 4 scores score(l',b,c) = dot(gap[l',b,:], W[c,:])
// (1K FMA + ~5 KB of L2-hot loads), softmax over l', pick this plane's
// scalar. Then multiply the arrived data and store. Removes the separate
// 8-block latency-bound attn kernel and its inter-kernel DRAM bubble.
// ---------------------------------------------------------------------------
__global__ __launch_bounds__(128) void scale_fused_kernel(const float* __restrict__ in,
                                                          const float* __restrict__ Wlin,
                                                          float* __restrict__ out) {
    const int bc = blockIdx.x;                 // (l*B + b)*C + c
    const int l = bc >> 11;                    // /2048
    const int b = (bc >> 8) & 7;
    const int c = bc & 255;
    const int t = threadIdx.x;

    const float4* p = reinterpret_cast<const float4*>(in) + (size_t)bc * (HW / 4);
    float4* o = reinterpret_cast<float4*>(out) + (size_t)bc * (HW / 4);

    // ---- Front-batch all 8 plane loads (independent LDG.128 in flight) ----
    float4 v0 = p[t + 0 * 128];
    float4 v1 = p[t + 1 * 128];
    float4 v2 = p[t + 2 * 128];
    float4 v3 = p[t + 3 * 128];
    float4 v4 = p[t + 4 * 128];
    float4 v5 = p[t + 5 * 128];
    float4 v6 = p[t + 6 * 128];
    float4 v7 = p[t + 7 * 128];

    // ---- Compute attn scalar while the plane loads are outstanding ----
    // Thread t covers c2 in {t, t+128}; 4 partial dots (one per l').
    const float* wr = Wlin + (size_t)c * C_DIM;
    float pa0 = 0.f, pa1 = 0.f, pa2 = 0.f, pa3 = 0.f;
#pragma unroll
    for (int j = 0; j < 2; ++j) {
        const int c2 = t + 128 * j;
        const float w = wr[c2];
        pa0 = fmaf(w, g_gap[(0 * B_DIM + b) * C_DIM + c2], pa0);
        pa1 = fmaf(w, g_gap[(1 * B_DIM + b) * C_DIM + c2], pa1);
        pa2 = fmaf(w, g_gap[(2 * B_DIM + b) * C_DIM + c2], pa2);
        pa3 = fmaf(w, g_gap[(3 * B_DIM + b) * C_DIM + c2], pa3);
    }
#pragma unroll
    for (int off = 16; off > 0; off >>= 1) {
        pa0 += __shfl_xor_sync(0xffffffffu, pa0, off);
        pa1 += __shfl_xor_sync(0xffffffffu, pa1, off);
        pa2 += __shfl_xor_sync(0xffffffffu, pa2, off);
        pa3 += __shfl_xor_sync(0xffffffffu, pa3, off);
    }
    __shared__ float sh[4][4];                 // [warp][l']
    const int warp = t >> 5;
    if ((t & 31) == 0) {
        sh[warp][0] = pa0; sh[warp][1] = pa1;
        sh[warp][2] = pa2; sh[warp][3] = pa3;
    }
    __syncthreads();
    const float s0 = sh[0][0] + sh[1][0] + sh[2][0] + sh[3][0];
    const float s1 = sh[0][1] + sh[1][1] + sh[2][1] + sh[3][1];
    const float s2 = sh[0][2] + sh[1][2] + sh[2][2] + sh[3][2];
    const float s3 = sh[0][3] + sh[1][3] + sh[2][3] + sh[3][3];

    const float m  = fmaxf(fmaxf(s0, s1), fmaxf(s2, s3));
    const float e0 = __expf(s0 - m), e1 = __expf(s1 - m);
    const float e2 = __expf(s2 - m), e3 = __expf(s3 - m);
    const float inv = 1.0f / (e0 + e1 + e2 + e3);
    const float el  = (l == 0) ? e0 : (l == 1) ? e1 : (l == 2) ? e2 : e3;
    const float a   = el * inv;

    // ---- Scale and store ----
    v0.x *= a; v0.y *= a; v0.z *= a; v0.w *= a;
    v1.x *= a; v1.y *= a; v1.z *= a; v1.w *= a;
    v2.x *= a; v2.y *= a; v2.z *= a; v2.w *= a;
    v3.x *= a; v3.y *= a; v3.z *= a; v3.w *= a;
    v4.x *= a; v4.y *= a; v4.z *= a; v4.w *= a;
    v5.x *= a; v5.y *= a; v5.z *= a; v5.w *= a;
    v6.x *= a; v6.y *= a; v6.z *= a; v6.w *= a;
    v7.x *= a; v7.y *= a; v7.z *= a; v7.w *= a;

    o[t + 0 * 128] = v0;
    o[t + 1 * 128] = v1;
    o[t + 2 * 128] = v2;
    o[t + 3 * 128] = v3;
    o[t + 4 * 128] = v4;
    o[t + 5 * 128] = v5;
    o[t + 6 * 128] = v6;
    o[t + 7 * 128] = v7;
}

extern "C" void kernel_launch(void* const* d_in, const int* in_sizes, int n_in,
                              void* d_out, int out_size) {
    const float* inputs = (const float*)d_in[0];   // [L,B,C,H,W] f32
    const float* Wlin   = (const float*)d_in[1];   // [C,C] f32
    float* out = (float*)d_out;

    gap_kernel<<<LBC, 128>>>(inputs);
    scale_fused_kernel<<<LBC, 128>>>(inputs, Wlin, out);
}